// round 13
// baseline (speedup 1.0000x reference)
#include <cuda_runtime.h>

#define K 48
#define STOPID 47
#define CHUNK 16
#define NWARP 4
#define CLAMPV 1e32f

typedef unsigned long long ull;

// ---------- packed f32x2 helpers (Blackwell sm_103a) ----------
__device__ __forceinline__ ull pack2(float x, float y) {
    ull r;
    asm("mov.b64 %0, {%1, %2};" : "=l"(r)
        : "r"(__float_as_uint(x)), "r"(__float_as_uint(y)));
    return r;
}
__device__ __forceinline__ void unpack2(ull v, float& x, float& y) {
    unsigned int a, b;
    asm("mov.b64 {%0, %1}, %2;" : "=r"(a), "=r"(b) : "l"(v));
    x = __uint_as_float(a);
    y = __uint_as_float(b);
}
__device__ __forceinline__ ull fma2(ull a, ull b, ull c) {
    ull d;
    asm("fma.rn.f32x2 %0, %1, %2, %3;" : "=l"(d) : "l"(a), "l"(b), "l"(c));
    return d;
}
__device__ __forceinline__ ull add2(ull a, ull b) {
    ull d;
    asm("add.rn.f32x2 %0, %1, %2;" : "=l"(d) : "l"(a), "l"(b));
    return d;
}
__device__ __forceinline__ void cp_async16(unsigned int s, const void* g) {
    asm volatile("cp.async.cg.shared.global [%0], [%1], 16;" :: "r"(s), "l"(g));
}

// One warp per sequence (512 warps, 1/SMSP — proven optimal geometry).
// 48x48 matvec as 96 half-rows: lane group h in {0,1} covers j in [24h,24h+24),
// lanes l16=0..15 own rows 3*l16..3*l16+2. Per lane: 36 fma2 (3-deep accs),
// 6 broadcast LDS.128, 1 shfl_xor(16) combine per row. After the combine BOTH
// halves hold the full p' -> all 32 lanes store, each group to its own smem
// copy; consumers read their own copy.
//
// R12 (single delta vs R9): NO per-step __syncwarp. The unrolled step body is
// branch-free -> the warp is converged; all lanes issue the STS before any
// lane reaches the next step's LDS, and the per-warp in-order LSU wavefront
// queue commits the stores first. The RAW through pb is a compiler-visible
// memory dependence (constant smem indices), so no reordering either. The
// chunk-boundary __syncwarp (cp.async buffer handoff) is retained.
//
// State in probability space: p' = exp(emit) * (E p), E = exp(trans) in 36
// packed regs. Emissions via cp.async double-buffered 16-step chunks. Renorm
// every 8th step by rcp(p0_of_input), rcp/log off the chain.
__global__ __launch_bounds__(128, 1) void crf_fwd_kernel(
    const float* __restrict__ h_tag,   // [B, T, K]
    const float* __restrict__ mask,    // [B, T]
    const float* __restrict__ trans,   // [K, K]
    float* __restrict__ out,           // [B]
    int B, int T)
{
    __shared__ __align__(16) float emb[NWARP][2][CHUNK * K];  // emit chunks
    __shared__ __align__(16) float mkb[NWARP][2][CHUNK];      // mask chunks
    __shared__ __align__(16) float pb [NWARP][2][2][K];       // [buf][copy][K]

    const int w    = threadIdx.x >> 5;
    const int lane = threadIdx.x & 31;
    const int b    = blockIdx.x * NWARP + w;
    if (b >= B) return;

    const int l16   = lane & 15;
    const int h     = lane >> 4;
    const int row0  = 3 * l16;
    const int jbase = 24 * h;

    // E2[r][m] = ( exp(trans[row0+r][jbase+2m]), exp(trans[row0+r][jbase+2m+1]) )
    ull E2[3][12];
#pragma unroll
    for (int r = 0; r < 3; r++) {
        const float* tr = trans + (row0 + r) * K + jbase;
#pragma unroll
        for (int m = 0; m < 12; m++)
            E2[r][m] = pack2(__expf(tr[2 * m]), __expf(tr[2 * m + 1]));
    }

    const float* hb = h_tag + (size_t)b * T * K;
    const float* mb = mask + (size_t)b * T;

    // init: score = NEG except STOP=0 -> c=-1e4, p=1 normal, p_STOP clamped to
    // 1e32 (feeds only the PAD track, ~e^4000 below answer; validated R3-R11).
    float pr[3], c = -1.0e4f;
#pragma unroll
    for (int r = 0; r < 3; r++) {
        pr[r] = (row0 + r == STOPID) ? CLAMPV : 1.0f;
        pb[w][0][h][row0 + r] = pr[r];   // both copies filled (h = 0 and 1)
    }

    const int nc    = (T + CHUNK - 1) / CHUNK;
    const int nfull = T / CHUNK;

    auto prefetch = [&](int ch) {
        const int t0n = ch * CHUNK;
        const int nb  = ch & 1;
        const size_t base = (size_t)t0n * K;
        unsigned int se = (unsigned int)__cvta_generic_to_shared(&emb[w][nb][0]);
#pragma unroll
        for (int i = 0; i < 6; i++) {     // CHUNK*K*4 = 3072B = 192 x 16B
            int seg = lane + 32 * i;
            if (base + (size_t)(seg + 1) * 4 <= (size_t)T * K)
                cp_async16(se + seg * 16, hb + base + seg * 4);
        }
        unsigned int sm = (unsigned int)__cvta_generic_to_shared(&mkb[w][nb][0]);
        if (lane < 4 && t0n + (lane + 1) * 4 <= T)
            cp_async16(sm + lane * 16, mb + t0n + lane * 4);
        asm volatile("cp.async.commit_group;");
    };

    prefetch(0);

    // ---------------- main: full 16-step chunks, 8-step unrolled bodies ----
    for (int ch = 0; ch < nfull; ch++) {
        const int cb = ch & 1;
        if (ch + 1 < nc) {
            prefetch(ch + 1);
            asm volatile("cp.async.wait_group 1;");
        } else {
            asm volatile("cp.async.wait_group 0;");
        }
        __syncwarp();   // chunk handoff: emit/mask buffers now visible

        for (int hf = 0; hf < 2; hf++) {
            const float* ebh = &emb[w][cb][hf * 8 * K + row0];
            const float* mkh = &mkb[w][cb][hf * 8];
#pragma unroll
            for (int s8 = 0; s8 < 8; s8++) {
                const int  rp = s8 & 1;        // read parity (hf*8 is even)
                const int  wp = rp ^ 1;
                const bool RN = (s8 == 7);     // compile-time renorm predicate

                // (no per-step syncwarp — see header comment)

                // chain head: p operands (own copy, broadcast LDS.128 x6)
                const ulonglong2* pu =
                    (const ulonglong2*)(&pb[w][rp][h][jbase]);
                ulonglong2 u0 = pu[0], u1 = pu[1], u2 = pu[2];
                ulonglong2 u3 = pu[3], u4 = pu[4], u5 = pu[5];

                float p0in = 1.0f;
                if (RN) p0in = pb[w][rp][h][0];     // early, off-chain use

                // off-chain: emissions + mask
                const float* eb = ebh + s8 * K;
                float ex0 = __expf(eb[0]);
                float ex1 = __expf(eb[1]);
                float ex2 = __expf(eb[2]);
                float mk  = mkh[s8];

                float rv = 1.0f, lv = 0.0f;
                if (RN) {
                    asm("rcp.approx.f32 %0, %1;" : "=f"(rv) : "f"(p0in));
                    lv = __logf(p0in);
                }

                // 36 fma2, 12 accumulators (3-deep chains)
                ull ax[3][2] = {{0,0},{0,0},{0,0}};
                ull ay[3][2] = {{0,0},{0,0},{0,0}};
                const ulonglong2 uu[6] = {u0, u1, u2, u3, u4, u5};
#pragma unroll
                for (int i = 0; i < 6; i++) {
                    const int par = i & 1;
#pragma unroll
                    for (int r = 0; r < 3; r++) {
                        ax[r][par] = fma2(E2[r][2 * i],     uu[i].x, ax[r][par]);
                        ay[r][par] = fma2(E2[r][2 * i + 1], uu[i].y, ay[r][par]);
                    }
                }

                float sr[3];
#pragma unroll
                for (int r = 0; r < 3; r++) {
                    ull tt = add2(add2(ax[r][0], ax[r][1]),
                                  add2(ay[r][0], ay[r][1]));
                    float x, y;
                    unpack2(tt, x, y);
                    sr[r] = x + y;
                }

                // combine halves: after this BOTH halves hold full p'
                sr[0] += __shfl_xor_sync(0xffffffffu, sr[0], 16);
                sr[1] += __shfl_xor_sync(0xffffffffu, sr[1], 16);
                sr[2] += __shfl_xor_sync(0xffffffffu, sr[2], 16);

                float n0 = fminf(ex0 * sr[0], CLAMPV);
                float n1 = fminf(ex1 * sr[1], CLAMPV);
                float n2 = fminf(ex2 * sr[2], CLAMPV);

                bool upd = (mk != 0.0f);
                pr[0] = upd ? n0 : pr[0];
                pr[1] = upd ? n1 : pr[1];
                pr[2] = upd ? n2 : pr[2];

                if (RN) {           // scale by rcp(p0_in): off-chain rcp/log
                    pr[0] *= rv; pr[1] *= rv; pr[2] *= rv;
                    c += lv;
                }

                // unconditional dual-copy store (no divergent branch)
                float* pd = &pb[w][wp][h][row0];
                pd[0] = pr[0]; pd[1] = pr[1]; pd[2] = pr[2];
            }
        }
    }

    // ---------------- tail (T % CHUNK != 0; unused for T=1024) -------------
    int t = nfull * CHUNK;
    if (t < T) {
        asm volatile("cp.async.wait_group 0;");
        const int cb = nfull & 1;
        for (int s = 0; t < T; s++, t++) {
            __syncwarp();
            const int rp = s & 1, wp = rp ^ 1;
            const ulonglong2* pu = (const ulonglong2*)(&pb[w][rp][h][jbase]);
            ulonglong2 uu[6];
#pragma unroll
            for (int i = 0; i < 6; i++) uu[i] = pu[i];
            const float* eb = &emb[w][cb][s * K + row0];
            float ex0 = __expf(eb[0]), ex1 = __expf(eb[1]), ex2 = __expf(eb[2]);
            float mk = mkb[w][cb][s];
            ull ax[3][2] = {{0,0},{0,0},{0,0}};
            ull ay[3][2] = {{0,0},{0,0},{0,0}};
#pragma unroll
            for (int i = 0; i < 6; i++) {
                const int par = i & 1;
#pragma unroll
                for (int r = 0; r < 3; r++) {
                    ax[r][par] = fma2(E2[r][2 * i],     uu[i].x, ax[r][par]);
                    ay[r][par] = fma2(E2[r][2 * i + 1], uu[i].y, ay[r][par]);
                }
            }
            float sr[3];
#pragma unroll
            for (int r = 0; r < 3; r++) {
                ull tt = add2(add2(ax[r][0], ax[r][1]), add2(ay[r][0], ay[r][1]));
                float x, y; unpack2(tt, x, y); sr[r] = x + y;
            }
            sr[0] += __shfl_xor_sync(0xffffffffu, sr[0], 16);
            sr[1] += __shfl_xor_sync(0xffffffffu, sr[1], 16);
            sr[2] += __shfl_xor_sync(0xffffffffu, sr[2], 16);
            float n0 = fminf(ex0 * sr[0], CLAMPV);
            float n1 = fminf(ex1 * sr[1], CLAMPV);
            float n2 = fminf(ex2 * sr[2], CLAMPV);
            bool upd = (mk != 0.0f);
            pr[0] = upd ? n0 : pr[0];
            pr[1] = upd ? n1 : pr[1];
            pr[2] = upd ? n2 : pr[2];
            if ((t & 7) == 7) {
                float d = __shfl_sync(0xffffffffu, pr[0], 0);
                float sc;
                asm("rcp.approx.f32 %0, %1;" : "=f"(sc) : "f"(d));
                pr[0] *= sc; pr[1] *= sc; pr[2] *= sc;
                c += __logf(d);
            }
            float* pd = &pb[w][wp][h][row0];
            pd[0] = pr[0]; pd[1] = pr[1]; pd[2] = pr[2];
        }
    }

    // ---------------- finalize: out = c + log( sum_k p_k e^{trans[STOP][k]} )
    // pr identical on both lane halves -> only lanes 0-15 contribute.
    float v = 0.0f;
    if (lane < 16) {
        const float* ts = trans + STOPID * K + row0;
        v = pr[0] * __expf(ts[0]) + pr[1] * __expf(ts[1]) + pr[2] * __expf(ts[2]);
    }
#pragma unroll
    for (int o = 16; o; o >>= 1)
        v += __shfl_xor_sync(0xffffffffu, v, o);
    if (lane == 0) out[b] = c + __logf(v);
}

extern "C" void kernel_launch(void* const* d_in, const int* in_sizes, int n_in,
                              void* d_out, int out_size)
{
    // Identify inputs by size: h_tag = largest, trans = smallest, mask = other
    int iH = 0, iT = 0;
    for (int i = 1; i < 3; i++) {
        if (in_sizes[i] > in_sizes[iH]) iH = i;
        if (in_sizes[i] < in_sizes[iT]) iT = i;
    }
    int iM = 3 - iH - iT;

    const float* h_tag = (const float*)d_in[iH];
    const float* mask  = (const float*)d_in[iM];
    const float* trans = (const float*)d_in[iT];
    float* out = (float*)d_out;

    int B = out_size;             // 512
    int T = in_sizes[iM] / B;     // 1024

    dim3 block(128);              // 4 warps, 1/SMSP, 1 sequence per warp
    dim3 grid((B + NWARP - 1) / NWARP);
    crf_fwd_kernel<<<grid, block>>>(h_tag, mask, trans, out, B, T);
}

// round 14
// speedup vs baseline: 1.0989x; 1.0989x over previous
#include <cuda_runtime.h>

#define K 48
#define STOPID 47
#define CHUNK 16
#define NWARP 4
#define CLAMPV 1e32f

typedef unsigned long long ull;

// ---------- packed f32x2 helpers (Blackwell sm_103a) ----------
__device__ __forceinline__ ull pack2(float x, float y) {
    ull r;
    asm("mov.b64 %0, {%1, %2};" : "=l"(r)
        : "r"(__float_as_uint(x)), "r"(__float_as_uint(y)));
    return r;
}
__device__ __forceinline__ void unpack2(ull v, float& x, float& y) {
    unsigned int a, b;
    asm("mov.b64 {%0, %1}, %2;" : "=r"(a), "=r"(b) : "l"(v));
    x = __uint_as_float(a);
    y = __uint_as_float(b);
}
__device__ __forceinline__ ull fma2(ull a, ull b, ull c) {
    ull d;
    asm("fma.rn.f32x2 %0, %1, %2, %3;" : "=l"(d) : "l"(a), "l"(b), "l"(c));
    return d;
}
__device__ __forceinline__ ull add2(ull a, ull b) {
    ull d;
    asm("add.rn.f32x2 %0, %1, %2;" : "=l"(d) : "l"(a), "l"(b));
    return d;
}
__device__ __forceinline__ void cp_async16(unsigned int s, const void* g) {
    asm volatile("cp.async.cg.shared.global [%0], [%1], 16;" :: "r"(s), "l"(g));
}

// One warp per sequence (512 warps, 1/SMSP — proven optimal geometry).
// 48x48 matvec as 96 half-rows: lane group h in {0,1} covers j in [24h,24h+24),
// lanes l16=0..15 own rows 3*l16..3*l16+2. Per lane: 36 fma2, 6 broadcast
// LDS.128, 1 shfl_xor(16) combine per row. After the combine BOTH halves hold
// full p' -> all 32 lanes store, each group to its own smem copy.
//
// R13 (two deltas vs the R9 champion):
//  1) Emission exp software-pipelined one step: step t uses ex/mk preloaded
//     during step t-1; prefetches step (t+1)&15 (branch-free wrap; the wrapped
//     stale value at a chunk boundary is never consumed — chunk start
//     re-preloads after the cp.async wait + syncwarp). Chain head is now
//     p-LDS -> fma burst with no emit LDS/MUFU in between.
//  2) 2 accumulators per row (6-deep chains, 12-cyc spacing): shorter tail.
//
// State in probability space: p' = exp(emit) * (E p), E = exp(trans) in 36
// packed regs. Renorm every 8th step by rcp(p0_of_input), rcp/log off-chain.
__global__ __launch_bounds__(128, 1) void crf_fwd_kernel(
    const float* __restrict__ h_tag,   // [B, T, K]
    const float* __restrict__ mask,    // [B, T]
    const float* __restrict__ trans,   // [K, K]
    float* __restrict__ out,           // [B]
    int B, int T)
{
    __shared__ __align__(16) float emb[NWARP][2][CHUNK * K];  // emit chunks
    __shared__ __align__(16) float mkb[NWARP][2][CHUNK];      // mask chunks
    __shared__ __align__(16) float pb [NWARP][2][2][K];       // [buf][copy][K]

    const int w    = threadIdx.x >> 5;
    const int lane = threadIdx.x & 31;
    const int b    = blockIdx.x * NWARP + w;
    if (b >= B) return;

    const int l16   = lane & 15;
    const int h     = lane >> 4;
    const int row0  = 3 * l16;
    const int jbase = 24 * h;

    // E2[r][m] = ( exp(trans[row0+r][jbase+2m]), exp(trans[row0+r][jbase+2m+1]) )
    ull E2[3][12];
#pragma unroll
    for (int r = 0; r < 3; r++) {
        const float* tr = trans + (row0 + r) * K + jbase;
#pragma unroll
        for (int m = 0; m < 12; m++)
            E2[r][m] = pack2(__expf(tr[2 * m]), __expf(tr[2 * m + 1]));
    }

    const float* hb = h_tag + (size_t)b * T * K;
    const float* mb = mask + (size_t)b * T;

    // init: score = NEG except STOP=0 -> c=-1e4, p=1 normal, p_STOP clamped to
    // 1e32 (feeds only the PAD track, ~e^4000 below answer; validated R3-R12).
    float pr[3], c = -1.0e4f;
#pragma unroll
    for (int r = 0; r < 3; r++) {
        pr[r] = (row0 + r == STOPID) ? CLAMPV : 1.0f;
        pb[w][0][h][row0 + r] = pr[r];   // both copies filled (h = 0 and 1)
    }

    const int nc    = (T + CHUNK - 1) / CHUNK;
    const int nfull = T / CHUNK;

    auto prefetch = [&](int ch) {
        const int t0n = ch * CHUNK;
        const int nb  = ch & 1;
        const size_t base = (size_t)t0n * K;
        unsigned int se = (unsigned int)__cvta_generic_to_shared(&emb[w][nb][0]);
#pragma unroll
        for (int i = 0; i < 6; i++) {     // CHUNK*K*4 = 3072B = 192 x 16B
            int seg = lane + 32 * i;
            if (base + (size_t)(seg + 1) * 4 <= (size_t)T * K)
                cp_async16(se + seg * 16, hb + base + seg * 4);
        }
        unsigned int sm = (unsigned int)__cvta_generic_to_shared(&mkb[w][nb][0]);
        if (lane < 4 && t0n + (lane + 1) * 4 <= T)
            cp_async16(sm + lane * 16, mb + t0n + lane * 4);
        asm volatile("cp.async.commit_group;");
    };

    prefetch(0);

    // ---------------- main: full 16-step chunks, 8-step unrolled bodies ----
    for (int ch = 0; ch < nfull; ch++) {
        const int cb = ch & 1;
        if (ch + 1 < nc) {
            prefetch(ch + 1);
            asm volatile("cp.async.wait_group 1;");
        } else {
            asm volatile("cp.async.wait_group 0;");
        }
        __syncwarp();   // chunk handoff: emit/mask buffers now visible

        // preload emissions/mask for step 0 of this chunk (off-chain)
        float exP0, exP1, exP2, mkP;
        {
            const float* e0 = &emb[w][cb][row0];
            exP0 = __expf(e0[0]);
            exP1 = __expf(e0[1]);
            exP2 = __expf(e0[2]);
            mkP  = mkb[w][cb][0];
        }

        for (int hf = 0; hf < 2; hf++) {
#pragma unroll
            for (int s8 = 0; s8 < 8; s8++) {
                const int  s  = hf * 8 + s8;   // hf runtime, s8 compile-time
                const int  rp = s8 & 1;        // read parity (hf*8 is even)
                const int  wp = rp ^ 1;
                const bool RN = (s8 == 7);     // compile-time renorm predicate

                __syncwarp();

                // chain head: p operands (own copy, broadcast LDS.128 x6)
                const ulonglong2* pu =
                    (const ulonglong2*)(&pb[w][rp][h][jbase]);
                ulonglong2 u0 = pu[0], u1 = pu[1], u2 = pu[2];
                ulonglong2 u3 = pu[3], u4 = pu[4], u5 = pu[5];

                float p0in = 1.0f;
                if (RN) p0in = pb[w][rp][h][0];     // early, off-chain use

                // prefetch NEXT step's emissions/mask ((s+1)&15: branch-free
                // wrap; wrapped value at chunk end is discarded — chunk start
                // re-preloads). Queued AFTER the chain-head p loads.
                const int sn = (s + 1) & 15;
                float exN0, exN1, exN2, mkN;
                {
                    const float* en = &emb[w][cb][sn * K + row0];
                    exN0 = __expf(en[0]);
                    exN1 = __expf(en[1]);
                    exN2 = __expf(en[2]);
                    mkN  = mkb[w][cb][sn];
                }

                float rv = 1.0f, lv = 0.0f;
                if (RN) {
                    asm("rcp.approx.f32 %0, %1;" : "=f"(rv) : "f"(p0in));
                    lv = __logf(p0in);
                }

                // 36 fma2, 2 accumulators per row (6-deep, 12-cyc spacing)
                ull aA[3] = {0, 0, 0};
                ull aB[3] = {0, 0, 0};
                const ulonglong2 uu[6] = {u0, u1, u2, u3, u4, u5};
#pragma unroll
                for (int i = 0; i < 6; i++) {
#pragma unroll
                    for (int r = 0; r < 3; r++) {
                        aA[r] = fma2(E2[r][2 * i],     uu[i].x, aA[r]);
                        aB[r] = fma2(E2[r][2 * i + 1], uu[i].y, aB[r]);
                    }
                }

                float sr[3];
#pragma unroll
                for (int r = 0; r < 3; r++) {
                    ull tt = add2(aA[r], aB[r]);
                    float x, y;
                    unpack2(tt, x, y);
                    sr[r] = x + y;
                }

                // combine halves: after this BOTH halves hold full p'
                sr[0] += __shfl_xor_sync(0xffffffffu, sr[0], 16);
                sr[1] += __shfl_xor_sync(0xffffffffu, sr[1], 16);
                sr[2] += __shfl_xor_sync(0xffffffffu, sr[2], 16);

                float n0 = fminf(exP0 * sr[0], CLAMPV);
                float n1 = fminf(exP1 * sr[1], CLAMPV);
                float n2 = fminf(exP2 * sr[2], CLAMPV);

                bool upd = (mkP != 0.0f);
                pr[0] = upd ? n0 : pr[0];
                pr[1] = upd ? n1 : pr[1];
                pr[2] = upd ? n2 : pr[2];

                if (RN) {           // scale by rcp(p0_in): off-chain rcp/log
                    pr[0] *= rv; pr[1] *= rv; pr[2] *= rv;
                    c += lv;
                }

                // unconditional dual-copy store (no divergent branch)
                float* pd = &pb[w][wp][h][row0];
                pd[0] = pr[0]; pd[1] = pr[1]; pd[2] = pr[2];

                // rotate emission pipeline
                exP0 = exN0; exP1 = exN1; exP2 = exN2; mkP = mkN;
            }
        }
    }

    // ---------------- tail (T % CHUNK != 0; unused for T=1024) -------------
    int t = nfull * CHUNK;
    if (t < T) {
        asm volatile("cp.async.wait_group 0;");
        const int cb = nfull & 1;
        for (int s = 0; t < T; s++, t++) {
            __syncwarp();
            const int rp = s & 1, wp = rp ^ 1;
            const ulonglong2* pu = (const ulonglong2*)(&pb[w][rp][h][jbase]);
            ulonglong2 uu[6];
#pragma unroll
            for (int i = 0; i < 6; i++) uu[i] = pu[i];
            const float* eb = &emb[w][cb][s * K + row0];
            float ex0 = __expf(eb[0]), ex1 = __expf(eb[1]), ex2 = __expf(eb[2]);
            float mk = mkb[w][cb][s];
            ull aA[3] = {0, 0, 0};
            ull aB[3] = {0, 0, 0};
#pragma unroll
            for (int i = 0; i < 6; i++) {
#pragma unroll
                for (int r = 0; r < 3; r++) {
                    aA[r] = fma2(E2[r][2 * i],     uu[i].x, aA[r]);
                    aB[r] = fma2(E2[r][2 * i + 1], uu[i].y, aB[r]);
                }
            }
            float sr[3];
#pragma unroll
            for (int r = 0; r < 3; r++) {
                ull tt = add2(aA[r], aB[r]);
                float x, y; unpack2(tt, x, y); sr[r] = x + y;
            }
            sr[0] += __shfl_xor_sync(0xffffffffu, sr[0], 16);
            sr[1] += __shfl_xor_sync(0xffffffffu, sr[1], 16);
            sr[2] += __shfl_xor_sync(0xffffffffu, sr[2], 16);
            float n0 = fminf(ex0 * sr[0], CLAMPV);
            float n1 = fminf(ex1 * sr[1], CLAMPV);
            float n2 = fminf(ex2 * sr[2], CLAMPV);
            bool upd = (mk != 0.0f);
            pr[0] = upd ? n0 : pr[0];
            pr[1] = upd ? n1 : pr[1];
            pr[2] = upd ? n2 : pr[2];
            if ((t & 7) == 7) {
                float d = __shfl_sync(0xffffffffu, pr[0], 0);
                float sc;
                asm("rcp.approx.f32 %0, %1;" : "=f"(sc) : "f"(d));
                pr[0] *= sc; pr[1] *= sc; pr[2] *= sc;
                c += __logf(d);
            }
            float* pd = &pb[w][wp][h][row0];
            pd[0] = pr[0]; pd[1] = pr[1]; pd[2] = pr[2];
        }
    }

    // ---------------- finalize: out = c + log( sum_k p_k e^{trans[STOP][k]} )
    // pr identical on both lane halves -> only lanes 0-15 contribute.
    float v = 0.0f;
    if (lane < 16) {
        const float* ts = trans + STOPID * K + row0;
        v = pr[0] * __expf(ts[0]) + pr[1] * __expf(ts[1]) + pr[2] * __expf(ts[2]);
    }
#pragma unroll
    for (int o = 16; o; o >>= 1)
        v += __shfl_xor_sync(0xffffffffu, v, o);
    if (lane == 0) out[b] = c + __logf(v);
}

extern "C" void kernel_launch(void* const* d_in, const int* in_sizes, int n_in,
                              void* d_out, int out_size)
{
    // Identify inputs by size: h_tag = largest, trans = smallest, mask = other
    int iH = 0, iT = 0;
    for (int i = 1; i < 3; i++) {
        if (in_sizes[i] > in_sizes[iH]) iH = i;
        if (in_sizes[i] < in_sizes[iT]) iT = i;
    }
    int iM = 3 - iH - iT;

    const float* h_tag = (const float*)d_in[iH];
    const float* mask  = (const float*)d_in[iM];
    const float* trans = (const float*)d_in[iT];
    float* out = (float*)d_out;

    int B = out_size;             // 512
    int T = in_sizes[iM] / B;     // 1024

    dim3 block(128);              // 4 warps, 1/SMSP, 1 sequence per warp
    dim3 grid((B + NWARP - 1) / NWARP);
    crf_fwd_kernel<<<grid, block>>>(h_tag, mask, trans, out, B, T);
}